// round 1
// baseline (speedup 1.0000x reference)
#include <cuda_runtime.h>

#define N_NODES 50000
#define N_EDGES 800000
#define D_IN    128
#define D_HID   256
#define D_OUT   128

// Scratch (no cudaMalloc allowed): agg [N,128] fp32, hidden [N,256] fp32
__device__ float g_agg[(size_t)N_NODES * D_IN];
__device__ float g_hid[(size_t)N_NODES * D_HID];

// ---------------------------------------------------------------------------
// Kernel 0: zero the aggregation buffer (float4 stores)
// ---------------------------------------------------------------------------
__global__ void zero_agg_kernel() {
    size_t i = (size_t)blockIdx.x * blockDim.x + threadIdx.x;
    size_t n = (size_t)N_NODES * D_IN / 4;
    if (i < n) reinterpret_cast<float4*>(g_agg)[i] = make_float4(0.f, 0.f, 0.f, 0.f);
}

// ---------------------------------------------------------------------------
// Kernel 1: edge aggregation.
// edge_dst is SORTED -> each warp owns a contiguous edge range, accumulates
// in registers while dst is unchanged, flushes with atomicAdd only on
// segment change / range end. Each lane owns 4 consecutive feature dims.
// ---------------------------------------------------------------------------
#define EDGES_PER_WARP 128

__global__ __launch_bounds__(256) void agg_kernel(
    const float* __restrict__ x,
    const int*   __restrict__ edge_src,
    const int*   __restrict__ edge_dst,
    const float* __restrict__ edge_val)
{
    int gtid   = blockIdx.x * blockDim.x + threadIdx.x;
    int warpId = gtid >> 5;
    int lane   = threadIdx.x & 31;

    long start = (long)warpId * EDGES_PER_WARP;
    if (start >= N_EDGES) return;
    long end = start + EDGES_PER_WARP;
    if (end > N_EDGES) end = N_EDGES;

    float ax = 0.f, ay = 0.f, az = 0.f, aw = 0.f;
    int cur_dst = edge_dst[start];

    for (long e = start; e < end; ++e) {
        int d = edge_dst[e];     // same addr across warp -> L1 broadcast
        if (d != cur_dst) {
            float* o = g_agg + (size_t)cur_dst * D_IN + lane * 4;
            atomicAdd(o + 0, ax);
            atomicAdd(o + 1, ay);
            atomicAdd(o + 2, az);
            atomicAdd(o + 3, aw);
            ax = ay = az = aw = 0.f;
            cur_dst = d;
        }
        int   s = edge_src[e];
        float v = edge_val[e];
        float4 xv = *reinterpret_cast<const float4*>(x + (size_t)s * D_IN + lane * 4);
        ax += v * xv.x;
        ay += v * xv.y;
        az += v * xv.z;
        aw += v * xv.w;
    }
    float* o = g_agg + (size_t)cur_dst * D_IN + lane * 4;
    atomicAdd(o + 0, ax);
    atomicAdd(o + 1, ay);
    atomicAdd(o + 2, az);
    atomicAdd(o + 3, aw);
}

// ---------------------------------------------------------------------------
// Kernel 2: GEMM1 fused:  hid = relu( (agg + (1+eps)*x) @ w1 + b1 )
// Classic SGEMM: BM=BN=128, BK=8, 256 threads, 8x8 micro-tile.
// A is built on the fly from g_agg and x.
// ---------------------------------------------------------------------------
__global__ __launch_bounds__(256) void gemm1_kernel(
    const float* __restrict__ x,
    const float* __restrict__ eps,
    const float* __restrict__ w1,
    const float* __restrict__ b1)
{
    const int M = N_NODES, N = D_HID, K = D_IN;
    __shared__ float As[8][128];
    __shared__ float Bs[8][128];

    const int tid = threadIdx.x;
    const int bm  = blockIdx.x;
    const int bn  = blockIdx.y;

    const float epsv = 1.0f + eps[0];

    // A tile loaders: 128 rows x 8 cols, one float4 per thread
    const int aRow = tid >> 1;
    const int aCol = (tid & 1) * 4;
    // B tile loaders: 8 rows x 128 cols, one float4 per thread
    const int bRow = tid >> 5;
    const int bCol = (tid & 31) * 4;
    // micro-tile position
    const int tRow = (tid >> 4) * 8;
    const int tCol = (tid & 15) * 8;

    const int gRow = bm * 128 + aRow;
    const bool rowOK = (gRow < M);
    const float* xrow = x     + (size_t)gRow * K;
    const float* arow = g_agg + (size_t)gRow * K;

    float acc[8][8];
    #pragma unroll
    for (int i = 0; i < 8; ++i)
        #pragma unroll
        for (int j = 0; j < 8; ++j) acc[i][j] = 0.f;

    for (int kt = 0; kt < K; kt += 8) {
        float4 av = make_float4(0.f, 0.f, 0.f, 0.f);
        if (rowOK) {
            float4 ag = *reinterpret_cast<const float4*>(arow + kt + aCol);
            float4 xx = *reinterpret_cast<const float4*>(xrow + kt + aCol);
            av.x = ag.x + epsv * xx.x;
            av.y = ag.y + epsv * xx.y;
            av.z = ag.z + epsv * xx.z;
            av.w = ag.w + epsv * xx.w;
        }
        As[aCol + 0][aRow] = av.x;
        As[aCol + 1][aRow] = av.y;
        As[aCol + 2][aRow] = av.z;
        As[aCol + 3][aRow] = av.w;

        *reinterpret_cast<float4*>(&Bs[bRow][bCol]) =
            *reinterpret_cast<const float4*>(w1 + (size_t)(kt + bRow) * N + bn * 128 + bCol);

        __syncthreads();

        #pragma unroll
        for (int k = 0; k < 8; ++k) {
            float rm[8], rn[8];
            *reinterpret_cast<float4*>(rm)     = *reinterpret_cast<float4*>(&As[k][tRow]);
            *reinterpret_cast<float4*>(rm + 4) = *reinterpret_cast<float4*>(&As[k][tRow + 4]);
            *reinterpret_cast<float4*>(rn)     = *reinterpret_cast<float4*>(&Bs[k][tCol]);
            *reinterpret_cast<float4*>(rn + 4) = *reinterpret_cast<float4*>(&Bs[k][tCol + 4]);
            #pragma unroll
            for (int i = 0; i < 8; ++i)
                #pragma unroll
                for (int j = 0; j < 8; ++j)
                    acc[i][j] += rm[i] * rn[j];
        }
        __syncthreads();
    }

    // epilogue: + b1, relu, store to g_hid
    float bv[8];
    #pragma unroll
    for (int j = 0; j < 8; ++j) bv[j] = b1[bn * 128 + tCol + j];

    #pragma unroll
    for (int i = 0; i < 8; ++i) {
        int row = bm * 128 + tRow + i;
        if (row >= M) break;
        float* o = g_hid + (size_t)row * N + bn * 128 + tCol;
        float v[8];
        #pragma unroll
        for (int j = 0; j < 8; ++j) {
            float t = acc[i][j] + bv[j];
            v[j] = t > 0.f ? t : 0.f;
        }
        *reinterpret_cast<float4*>(o)     = make_float4(v[0], v[1], v[2], v[3]);
        *reinterpret_cast<float4*>(o + 4) = make_float4(v[4], v[5], v[6], v[7]);
    }
}

// ---------------------------------------------------------------------------
// Kernel 3: GEMM2:  out = hid @ w2 + b2
// Same SGEMM structure, K=256, N=128.
// ---------------------------------------------------------------------------
__global__ __launch_bounds__(256) void gemm2_kernel(
    const float* __restrict__ w2,
    const float* __restrict__ b2,
    float*       __restrict__ out)
{
    const int M = N_NODES, N = D_OUT, K = D_HID;
    __shared__ float As[8][128];
    __shared__ float Bs[8][128];

    const int tid = threadIdx.x;
    const int bm  = blockIdx.x;

    const int aRow = tid >> 1;
    const int aCol = (tid & 1) * 4;
    const int bRow = tid >> 5;
    const int bCol = (tid & 31) * 4;
    const int tRow = (tid >> 4) * 8;
    const int tCol = (tid & 15) * 8;

    const int gRow = bm * 128 + aRow;
    const bool rowOK = (gRow < M);
    const float* arow = g_hid + (size_t)gRow * K;

    float acc[8][8];
    #pragma unroll
    for (int i = 0; i < 8; ++i)
        #pragma unroll
        for (int j = 0; j < 8; ++j) acc[i][j] = 0.f;

    for (int kt = 0; kt < K; kt += 8) {
        float4 av = make_float4(0.f, 0.f, 0.f, 0.f);
        if (rowOK) av = *reinterpret_cast<const float4*>(arow + kt + aCol);
        As[aCol + 0][aRow] = av.x;
        As[aCol + 1][aRow] = av.y;
        As[aCol + 2][aRow] = av.z;
        As[aCol + 3][aRow] = av.w;

        *reinterpret_cast<float4*>(&Bs[bRow][bCol]) =
            *reinterpret_cast<const float4*>(w2 + (size_t)(kt + bRow) * N + bCol);

        __syncthreads();

        #pragma unroll
        for (int k = 0; k < 8; ++k) {
            float rm[8], rn[8];
            *reinterpret_cast<float4*>(rm)     = *reinterpret_cast<float4*>(&As[k][tRow]);
            *reinterpret_cast<float4*>(rm + 4) = *reinterpret_cast<float4*>(&As[k][tRow + 4]);
            *reinterpret_cast<float4*>(rn)     = *reinterpret_cast<float4*>(&Bs[k][tCol]);
            *reinterpret_cast<float4*>(rn + 4) = *reinterpret_cast<float4*>(&Bs[k][tCol + 4]);
            #pragma unroll
            for (int i = 0; i < 8; ++i)
                #pragma unroll
                for (int j = 0; j < 8; ++j)
                    acc[i][j] += rm[i] * rn[j];
        }
        __syncthreads();
    }

    float bv[8];
    #pragma unroll
    for (int j = 0; j < 8; ++j) bv[j] = b2[tCol + j];

    #pragma unroll
    for (int i = 0; i < 8; ++i) {
        int row = bm * 128 + tRow + i;
        if (row >= M) break;
        float* o = out + (size_t)row * N + tCol;
        float v[8];
        #pragma unroll
        for (int j = 0; j < 8; ++j) v[j] = acc[i][j] + bv[j];
        *reinterpret_cast<float4*>(o)     = make_float4(v[0], v[1], v[2], v[3]);
        *reinterpret_cast<float4*>(o + 4) = make_float4(v[4], v[5], v[6], v[7]);
    }
}

// ---------------------------------------------------------------------------
// Launch
// Inputs (metadata order): x, edge_src, edge_dst, edge_val, eps, w1, b1, w2, b2
// ---------------------------------------------------------------------------
extern "C" void kernel_launch(void* const* d_in, const int* in_sizes, int n_in,
                              void* d_out, int out_size)
{
    const float* x        = (const float*)d_in[0];
    const int*   edge_src = (const int*)  d_in[1];
    const int*   edge_dst = (const int*)  d_in[2];
    const float* edge_val = (const float*)d_in[3];
    const float* eps      = (const float*)d_in[4];
    const float* w1       = (const float*)d_in[5];
    const float* b1       = (const float*)d_in[6];
    const float* w2       = (const float*)d_in[7];
    const float* b2       = (const float*)d_in[8];
    float* out = (float*)d_out;

    // zero agg buffer
    {
        size_t n = (size_t)N_NODES * D_IN / 4;
        int blocks = (int)((n + 255) / 256);
        zero_agg_kernel<<<blocks, 256>>>();
    }
    // aggregation
    {
        int warps  = (N_EDGES + EDGES_PER_WARP - 1) / EDGES_PER_WARP;
        int blocks = (warps * 32 + 255) / 256;
        agg_kernel<<<blocks, 256>>>(x, edge_src, edge_dst, edge_val);
    }
    // GEMM1 (fused agg + (1+eps)x, bias, relu)
    {
        dim3 grid((N_NODES + 127) / 128, D_HID / 128);
        gemm1_kernel<<<grid, 256>>>(x, eps, w1, b1);
    }
    // GEMM2 (bias)
    {
        dim3 grid((N_NODES + 127) / 128, D_OUT / 128);
        gemm2_kernel<<<grid, 256>>>(w2, b2, out);
    }
}

// round 3
// speedup vs baseline: 1.5350x; 1.5350x over previous
#include <cuda_runtime.h>
#include <cuda_bf16.h>
#include <cstdint>

#define N_NODES 50000
#define N_EDGES 800000
#define D_IN    128
#define D_HID   256
#define D_OUT   128

// ---------------------------------------------------------------------------
// Device scratch (no cudaMalloc allowed)
// ---------------------------------------------------------------------------
__device__ float         g_agg   [(size_t)N_NODES * D_IN];
__device__ __nv_bfloat16 g_hid_hi[(size_t)N_NODES * D_HID];
__device__ __nv_bfloat16 g_hid_lo[(size_t)N_NODES * D_HID];
__device__ __nv_bfloat16 g_b1_hi [D_HID * D_IN];    // w1^T split [256,128]
__device__ __nv_bfloat16 g_b1_lo [D_HID * D_IN];
__device__ __nv_bfloat16 g_b2_hi [D_OUT * D_HID];   // w2^T split [128,256]
__device__ __nv_bfloat16 g_b2_lo [D_OUT * D_HID];

// ---------------------------------------------------------------------------
// helpers
// ---------------------------------------------------------------------------
__device__ __forceinline__ uint32_t smem_u32(const void* p) {
    uint32_t a;
    asm("{ .reg .u64 t; cvta.to.shared.u64 t, %1; cvt.u32.u64 %0, t; }" : "=r"(a) : "l"(p));
    return a;
}
__device__ __forceinline__ uint32_t sw128(uint32_t off) { return off ^ ((off >> 3) & 0x70); }

__device__ __forceinline__ uint32_t pack2bf(float a, float b) {
    __nv_bfloat16 ha = __float2bfloat16_rn(a), hb = __float2bfloat16_rn(b);
    return (uint32_t)__bfloat16_as_ushort(ha) | ((uint32_t)__bfloat16_as_ushort(hb) << 16);
}

__device__ __forceinline__ void ldsm_x4(uint32_t* r, uint32_t addr) {
    asm volatile("ldmatrix.sync.aligned.m8n8.x4.shared.b16 {%0,%1,%2,%3}, [%4];"
                 : "=r"(r[0]), "=r"(r[1]), "=r"(r[2]), "=r"(r[3]) : "r"(addr));
}
__device__ __forceinline__ void mma_bf16(float* c, const uint32_t* a, uint32_t b0, uint32_t b1) {
    asm volatile("mma.sync.aligned.m16n8k16.row.col.f32.bf16.bf16.f32 "
                 "{%0,%1,%2,%3}, {%4,%5,%6,%7}, {%8,%9}, {%0,%1,%2,%3};"
                 : "+f"(c[0]), "+f"(c[1]), "+f"(c[2]), "+f"(c[3])
                 : "r"(a[0]), "r"(a[1]), "r"(a[2]), "r"(a[3]), "r"(b0), "r"(b1));
}
__device__ __forceinline__ void sts16(uint32_t addr, uint4 v) {
    asm volatile("st.shared.v4.b32 [%0], {%1,%2,%3,%4};"
                 :: "r"(addr), "r"(v.x), "r"(v.y), "r"(v.z), "r"(v.w) : "memory");
}

// ---------------------------------------------------------------------------
// zero agg buffer
// ---------------------------------------------------------------------------
__global__ void zero_agg_kernel() {
    size_t i = (size_t)blockIdx.x * blockDim.x + threadIdx.x;
    size_t n = (size_t)N_NODES * D_IN / 4;
    if (i < n) reinterpret_cast<float4*>(g_agg)[i] = make_float4(0.f, 0.f, 0.f, 0.f);
}

// ---------------------------------------------------------------------------
// edge aggregation (edge_dst sorted -> register accumulation per run)
// ---------------------------------------------------------------------------
#define EDGES_PER_WARP 128

__global__ __launch_bounds__(256) void agg_kernel(
    const float* __restrict__ x,
    const int*   __restrict__ edge_src,
    const int*   __restrict__ edge_dst,
    const float* __restrict__ edge_val)
{
    int gtid   = blockIdx.x * blockDim.x + threadIdx.x;
    int warpId = gtid >> 5;
    int lane   = threadIdx.x & 31;

    long start = (long)warpId * EDGES_PER_WARP;
    if (start >= N_EDGES) return;
    long end = start + EDGES_PER_WARP;
    if (end > N_EDGES) end = N_EDGES;

    float ax = 0.f, ay = 0.f, az = 0.f, aw = 0.f;
    int cur_dst = edge_dst[start];

    for (long e = start; e < end; ++e) {
        int d = edge_dst[e];
        if (d != cur_dst) {
            float* o = g_agg + (size_t)cur_dst * D_IN + lane * 4;
            atomicAdd(o + 0, ax); atomicAdd(o + 1, ay);
            atomicAdd(o + 2, az); atomicAdd(o + 3, aw);
            ax = ay = az = aw = 0.f;
            cur_dst = d;
        }
        int   s = edge_src[e];
        float v = edge_val[e];
        float4 xv = *reinterpret_cast<const float4*>(x + (size_t)s * D_IN + lane * 4);
        ax += v * xv.x; ay += v * xv.y; az += v * xv.z; aw += v * xv.w;
    }
    float* o = g_agg + (size_t)cur_dst * D_IN + lane * 4;
    atomicAdd(o + 0, ax); atomicAdd(o + 1, ay);
    atomicAdd(o + 2, az); atomicAdd(o + 3, aw);
}

// ---------------------------------------------------------------------------
// weight transpose + split
// ---------------------------------------------------------------------------
__global__ __launch_bounds__(256) void conv_b_kernel(const float* __restrict__ w1,
                                                     const float* __restrict__ w2)
{
    int idx = blockIdx.x * blockDim.x + threadIdx.x;
    if (idx < D_HID * D_IN) {
        int n = idx / D_IN, k = idx % D_IN;
        float v = w1[(size_t)k * D_HID + n];
        __nv_bfloat16 h = __float2bfloat16_rn(v);
        g_b1_hi[idx] = h;
        g_b1_lo[idx] = __float2bfloat16_rn(v - __bfloat162float(h));
    }
    int idx2 = idx - D_HID * D_IN;
    if (idx2 >= 0 && idx2 < D_OUT * D_HID) {
        int n = idx2 / D_HID, k = idx2 % D_HID;
        float v = w2[(size_t)k * D_OUT + n];
        __nv_bfloat16 h = __float2bfloat16_rn(v);
        g_b2_hi[idx2] = h;
        g_b2_lo[idx2] = __float2bfloat16_rn(v - __bfloat162float(h));
    }
}

// ---------------------------------------------------------------------------
// mma.sync split-bf16 GEMM.
//   Block tile 128x128, BK=64, 8 warps, warp tile 32x64 (2x8 m16n8 tiles).
//   AMODE 0: A built on the fly from g_agg + (1+eps)*x (fp32 -> split bf16)
//   AMODE 1: A read from a_hi/a_lo (bf16)
//   SPLIT:   epilogue bias+ReLU, write split bf16; else bias, write fp32.
//   SMEM: A_hi | A_lo | B_hi | B_lo, each 128x64 bf16 = 16 KB (SW128 rows).
// ---------------------------------------------------------------------------
template <int K, int NTOT, int AMODE, bool SPLIT>
__global__ __launch_bounds__(256) void gemm_mma_kernel(
    const float* __restrict__ aggp,
    const float* __restrict__ xp,
    const float* __restrict__ eps,
    const __nv_bfloat16* __restrict__ a_hi,
    const __nv_bfloat16* __restrict__ a_lo,
    const __nv_bfloat16* __restrict__ b_hi,
    const __nv_bfloat16* __restrict__ b_lo,
    const float* __restrict__ bias,
    __nv_bfloat16* __restrict__ o_hi,
    __nv_bfloat16* __restrict__ o_lo,
    float* __restrict__ o_f32)
{
    constexpr uint32_t A_HI = 0, A_LO = 16384, B_HI = 32768, B_LO = 49152;

    extern __shared__ char smem[];
    const uint32_t sb = smem_u32(smem);

    const int tid   = threadIdx.x;
    const int lane  = tid & 31;
    const int wid   = tid >> 5;
    const int wm0   = (wid & 3) * 32;   // warp row offset in block tile
    const int wn0   = (wid >> 2) * 64;  // warp col offset
    const int row0  = blockIdx.x * 128;
    const int ncol0 = blockIdx.y * 128;

    float epsv = 0.f;
    if (AMODE == 0) epsv = 1.0f + eps[0];

    float acc[2][8][4];
    #pragma unroll
    for (int i = 0; i < 2; ++i)
        #pragma unroll
        for (int j = 0; j < 8; ++j)
            #pragma unroll
            for (int q = 0; q < 4; ++q) acc[i][j][q] = 0.f;

    for (int kc = 0; kc < K / 64; ++kc) {
        // -------- stage A --------
        if (AMODE == 0) {
            #pragma unroll
            for (int u = tid; u < 1024; u += 256) {
                int r = u >> 3, g = u & 7;
                int row = row0 + r;
                int k0 = kc * 64 + g * 8;
                uint4 hi = make_uint4(0, 0, 0, 0), lo = make_uint4(0, 0, 0, 0);
                if (row < N_NODES) {
                    const float* pa = aggp + (size_t)row * K + k0;
                    const float* px = xp   + (size_t)row * K + k0;
                    float4 a0 = *reinterpret_cast<const float4*>(pa);
                    float4 a1 = *reinterpret_cast<const float4*>(pa + 4);
                    float4 x0 = *reinterpret_cast<const float4*>(px);
                    float4 x1 = *reinterpret_cast<const float4*>(px + 4);
                    float v[8];
                    v[0] = a0.x + epsv * x0.x; v[1] = a0.y + epsv * x0.y;
                    v[2] = a0.z + epsv * x0.z; v[3] = a0.w + epsv * x0.w;
                    v[4] = a1.x + epsv * x1.x; v[5] = a1.y + epsv * x1.y;
                    v[6] = a1.z + epsv * x1.z; v[7] = a1.w + epsv * x1.w;
                    float h[8], l[8];
                    #pragma unroll
                    for (int j = 0; j < 8; ++j) {
                        h[j] = __bfloat162float(__float2bfloat16_rn(v[j]));
                        l[j] = v[j] - h[j];
                    }
                    hi = make_uint4(pack2bf(h[0], h[1]), pack2bf(h[2], h[3]),
                                    pack2bf(h[4], h[5]), pack2bf(h[6], h[7]));
                    lo = make_uint4(pack2bf(l[0], l[1]), pack2bf(l[2], l[3]),
                                    pack2bf(l[4], l[5]), pack2bf(l[6], l[7]));
                }
                uint32_t off = sw128((uint32_t)(r * 128 + g * 16));
                sts16(sb + A_HI + off, hi);
                sts16(sb + A_LO + off, lo);
            }
        } else {
            #pragma unroll
            for (int u = tid; u < 2048; u += 256) {
                int buf = u >> 10, rem = u & 1023;
                int r = rem >> 3, g = rem & 7;
                int row = row0 + r;
                uint4 v = make_uint4(0, 0, 0, 0);
                if (row < N_NODES) {
                    const __nv_bfloat16* src = (buf ? a_lo : a_hi) +
                        (size_t)row * K + kc * 64 + g * 8;
                    v = *reinterpret_cast<const uint4*>(src);
                }
                uint32_t off = sw128((uint32_t)(r * 128 + g * 16));
                sts16(sb + (buf ? A_LO : A_HI) + off, v);
            }
        }
        // -------- stage B --------
        #pragma unroll
        for (int u = tid; u < 2048; u += 256) {
            int buf = u >> 10, rem = u & 1023;
            int r = rem >> 3, g = rem & 7;
            const __nv_bfloat16* src = (buf ? b_lo : b_hi) +
                (size_t)(ncol0 + r) * K + kc * 64 + g * 8;
            uint4 v = *reinterpret_cast<const uint4*>(src);
            uint32_t off = sw128((uint32_t)(r * 128 + g * 16));
            sts16(sb + (buf ? B_LO : B_HI) + off, v);
        }
        __syncthreads();

        // -------- MMA over 4 k16 steps --------
        #pragma unroll
        for (int ks = 0; ks < 4; ++ks) {
            const int kb = ks * 32;
            uint32_t afh[2][4], afl[2][4];
            #pragma unroll
            for (int mi = 0; mi < 2; ++mi) {
                uint32_t off = sw128((uint32_t)((wm0 + mi * 16 + (lane & 15)) * 128 +
                                                kb + (lane >> 4) * 16));
                ldsm_x4(afh[mi], sb + A_HI + off);
                ldsm_x4(afl[mi], sb + A_LO + off);
            }
            uint32_t bfh[4][4], bfl[4][4];
            #pragma unroll
            for (int pi = 0; pi < 4; ++pi) {
                int q = lane >> 3;
                uint32_t off = sw128((uint32_t)(
                    (wn0 + pi * 16 + ((q >> 1) << 3) + (lane & 7)) * 128 +
                    kb + (q & 1) * 16));
                ldsm_x4(bfh[pi], sb + B_HI + off);
                ldsm_x4(bfl[pi], sb + B_LO + off);
            }
            #pragma unroll
            for (int mi = 0; mi < 2; ++mi) {
                #pragma unroll
                for (int ni = 0; ni < 8; ++ni) {
                    const int pi = ni >> 1, h = (ni & 1) * 2;
                    mma_bf16(acc[mi][ni], afh[mi], bfh[pi][h], bfh[pi][h + 1]);
                    mma_bf16(acc[mi][ni], afl[mi], bfh[pi][h], bfh[pi][h + 1]);
                    mma_bf16(acc[mi][ni], afh[mi], bfl[pi][h], bfl[pi][h + 1]);
                }
            }
        }
        __syncthreads();
    }

    // -------- epilogue --------
    #pragma unroll
    for (int mi = 0; mi < 2; ++mi) {
        #pragma unroll
        for (int ni = 0; ni < 8; ++ni) {
            int col = ncol0 + wn0 + ni * 8 + (lane & 3) * 2;
            int rbase = row0 + wm0 + mi * 16 + (lane >> 2);
            float2 bb = *reinterpret_cast<const float2*>(bias + col);
            #pragma unroll
            for (int p = 0; p < 2; ++p) {
                int row = rbase + p * 8;
                if (row >= N_NODES) continue;
                float v0 = acc[mi][ni][2 * p]     + bb.x;
                float v1 = acc[mi][ni][2 * p + 1] + bb.y;
                if (SPLIT) {
                    v0 = fmaxf(v0, 0.f); v1 = fmaxf(v1, 0.f);
                    float h0 = __bfloat162float(__float2bfloat16_rn(v0));
                    float h1 = __bfloat162float(__float2bfloat16_rn(v1));
                    *reinterpret_cast<uint32_t*>(o_hi + (size_t)row * NTOT + col) =
                        pack2bf(h0, h1);
                    *reinterpret_cast<uint32_t*>(o_lo + (size_t)row * NTOT + col) =
                        pack2bf(v0 - h0, v1 - h1);
                } else {
                    *reinterpret_cast<float2*>(o_f32 + (size_t)row * NTOT + col) =
                        make_float2(v0, v1);
                }
            }
        }
    }
}

// ---------------------------------------------------------------------------
// Launch. Inputs: x, edge_src, edge_dst, edge_val, eps, w1, b1, w2, b2
// ---------------------------------------------------------------------------
extern "C" void kernel_launch(void* const* d_in, const int* in_sizes, int n_in,
                              void* d_out, int out_size)
{
    const float* x        = (const float*)d_in[0];
    const int*   edge_src = (const int*)  d_in[1];
    const int*   edge_dst = (const int*)  d_in[2];
    const float* edge_val = (const float*)d_in[3];
    const float* eps      = (const float*)d_in[4];
    const float* w1       = (const float*)d_in[5];
    const float* b1       = (const float*)d_in[6];
    const float* w2       = (const float*)d_in[7];
    const float* b2       = (const float*)d_in[8];
    float* out = (float*)d_out;

    float* aggp;
    __nv_bfloat16 *hid_hi, *hid_lo, *b1h, *b1l, *b2h, *b2l;
    cudaGetSymbolAddress((void**)&aggp,   g_agg);
    cudaGetSymbolAddress((void**)&hid_hi, g_hid_hi);
    cudaGetSymbolAddress((void**)&hid_lo, g_hid_lo);
    cudaGetSymbolAddress((void**)&b1h, g_b1_hi);
    cudaGetSymbolAddress((void**)&b1l, g_b1_lo);
    cudaGetSymbolAddress((void**)&b2h, g_b2_hi);
    cudaGetSymbolAddress((void**)&b2l, g_b2_lo);

    // zero agg
    {
        size_t n = (size_t)N_NODES * D_IN / 4;
        zero_agg_kernel<<<(int)((n + 255) / 256), 256>>>();
    }
    // aggregation
    {
        int warps = (N_EDGES + EDGES_PER_WARP - 1) / EDGES_PER_WARP;
        agg_kernel<<<(warps * 32 + 255) / 256, 256>>>(x, edge_src, edge_dst, edge_val);
    }
    // weight transpose + split
    conv_b_kernel<<<(D_HID * D_IN + D_OUT * D_HID + 255) / 256, 256>>>(w1, w2);

    const int grid_m = (N_NODES + 127) / 128;
    constexpr int SMEM = 65536;

    // GEMM1: A = agg + (1+eps)x on the fly; [N,128] x [128,256] -> hid split
    {
        auto kfn = gemm_mma_kernel<D_IN, D_HID, 0, true>;
        cudaFuncSetAttribute(kfn, cudaFuncAttributeMaxDynamicSharedMemorySize, SMEM);
        kfn<<<dim3(grid_m, D_HID / 128), 256, SMEM>>>(
            aggp, x, eps, nullptr, nullptr, b1h, b1l, b1, hid_hi, hid_lo, nullptr);
    }
    // GEMM2: [N,256] x [256,128] -> out fp32
    {
        auto kfn = gemm_mma_kernel<D_HID, D_OUT, 1, false>;
        cudaFuncSetAttribute(kfn, cudaFuncAttributeMaxDynamicSharedMemorySize, SMEM);
        kfn<<<dim3(grid_m, 1), 256, SMEM>>>(
            nullptr, nullptr, nullptr, hid_hi, hid_lo, b2h, b2l, b2,
            nullptr, nullptr, out);
    }
}

// round 4
// speedup vs baseline: 1.8778x; 1.2233x over previous
#include <cuda_runtime.h>
#include <cuda_bf16.h>
#include <cstdint>

#define N_NODES 50000
#define N_EDGES 800000
#define D_IN    128
#define D_HID   256
#define D_OUT   128

// ---------------------------------------------------------------------------
// Device scratch (no cudaMalloc allowed)
// ---------------------------------------------------------------------------
__device__ float         g_agg   [(size_t)N_NODES * D_IN];
__device__ __nv_bfloat16 g_hid_hi[(size_t)N_NODES * D_HID];
__device__ __nv_bfloat16 g_hid_lo[(size_t)N_NODES * D_HID];
__device__ __nv_bfloat16 g_b1_hi [D_HID * D_IN];    // w1^T split [256,128]
__device__ __nv_bfloat16 g_b1_lo [D_HID * D_IN];
__device__ __nv_bfloat16 g_b2_hi [D_OUT * D_HID];   // w2^T split [128,256]
__device__ __nv_bfloat16 g_b2_lo [D_OUT * D_HID];

// ---------------------------------------------------------------------------
// helpers
// ---------------------------------------------------------------------------
__device__ __forceinline__ uint32_t smem_u32(const void* p) {
    uint32_t a;
    asm("{ .reg .u64 t; cvta.to.shared.u64 t, %1; cvt.u32.u64 %0, t; }" : "=r"(a) : "l"(p));
    return a;
}
__device__ __forceinline__ uint32_t sw128(uint32_t off) { return off ^ ((off >> 3) & 0x70); }

__device__ __forceinline__ uint32_t pack2bf(float a, float b) {
    __nv_bfloat16 ha = __float2bfloat16_rn(a), hb = __float2bfloat16_rn(b);
    return (uint32_t)__bfloat16_as_ushort(ha) | ((uint32_t)__bfloat16_as_ushort(hb) << 16);
}
__device__ __forceinline__ void ldsm_x4(uint32_t* r, uint32_t addr) {
    asm volatile("ldmatrix.sync.aligned.m8n8.x4.shared.b16 {%0,%1,%2,%3}, [%4];"
                 : "=r"(r[0]), "=r"(r[1]), "=r"(r[2]), "=r"(r[3]) : "r"(addr));
}
__device__ __forceinline__ void mma_bf16(float* c, const uint32_t* a, uint32_t b0, uint32_t b1) {
    asm volatile("mma.sync.aligned.m16n8k16.row.col.f32.bf16.bf16.f32 "
                 "{%0,%1,%2,%3}, {%4,%5,%6,%7}, {%8,%9}, {%0,%1,%2,%3};"
                 : "+f"(c[0]), "+f"(c[1]), "+f"(c[2]), "+f"(c[3])
                 : "r"(a[0]), "r"(a[1]), "r"(a[2]), "r"(a[3]), "r"(b0), "r"(b1));
}
__device__ __forceinline__ void sts16(uint32_t addr, uint4 v) {
    asm volatile("st.shared.v4.b32 [%0], {%1,%2,%3,%4};"
                 :: "r"(addr), "r"(v.x), "r"(v.y), "r"(v.z), "r"(v.w) : "memory");
}
// cp.async 16B with runtime src-size (0 -> zero-fill, no access)
__device__ __forceinline__ void cp16(uint32_t dst, const void* src, uint32_t sz) {
    asm volatile("cp.async.cg.shared.global [%0], [%1], 16, %2;"
                 :: "r"(dst), "l"(src), "r"(sz) : "memory");
}
__device__ __forceinline__ void cp_commit_wait() {
    asm volatile("cp.async.commit_group;" ::: "memory");
    asm volatile("cp.async.wait_group 0;" ::: "memory");
}

// ---------------------------------------------------------------------------
// init agg buffer with (1+eps)*x   (so agg accumulates edges on top)
// ---------------------------------------------------------------------------
__global__ void init_agg_kernel(const float* __restrict__ x,
                                const float* __restrict__ eps) {
    const float epsv = 1.0f + eps[0];
    size_t i = (size_t)blockIdx.x * blockDim.x + threadIdx.x;
    size_t n = (size_t)N_NODES * D_IN / 4;
    if (i < n) {
        float4 v = reinterpret_cast<const float4*>(x)[i];
        v.x *= epsv; v.y *= epsv; v.z *= epsv; v.w *= epsv;
        reinterpret_cast<float4*>(g_agg)[i] = v;
    }
}

// ---------------------------------------------------------------------------
// edge aggregation (edge_dst sorted -> register accumulation per run)
// ---------------------------------------------------------------------------
#define EDGES_PER_WARP 128

__global__ __launch_bounds__(256) void agg_kernel(
    const float* __restrict__ x,
    const int*   __restrict__ edge_src,
    const int*   __restrict__ edge_dst,
    const float* __restrict__ edge_val)
{
    int gtid   = blockIdx.x * blockDim.x + threadIdx.x;
    int warpId = gtid >> 5;
    int lane   = threadIdx.x & 31;

    long start = (long)warpId * EDGES_PER_WARP;
    if (start >= N_EDGES) return;
    long end = start + EDGES_PER_WARP;
    if (end > N_EDGES) end = N_EDGES;

    float ax = 0.f, ay = 0.f, az = 0.f, aw = 0.f;
    int cur_dst = edge_dst[start];

    for (long e = start; e < end; ++e) {
        int d = edge_dst[e];
        if (d != cur_dst) {
            float* o = g_agg + (size_t)cur_dst * D_IN + lane * 4;
            atomicAdd(o + 0, ax); atomicAdd(o + 1, ay);
            atomicAdd(o + 2, az); atomicAdd(o + 3, aw);
            ax = ay = az = aw = 0.f;
            cur_dst = d;
        }
        int   s = edge_src[e];
        float v = edge_val[e];
        float4 xv = *reinterpret_cast<const float4*>(x + (size_t)s * D_IN + lane * 4);
        ax += v * xv.x; ay += v * xv.y; az += v * xv.z; aw += v * xv.w;
    }
    float* o = g_agg + (size_t)cur_dst * D_IN + lane * 4;
    atomicAdd(o + 0, ax); atomicAdd(o + 1, ay);
    atomicAdd(o + 2, az); atomicAdd(o + 3, aw);
}

// ---------------------------------------------------------------------------
// weight transpose + split
// ---------------------------------------------------------------------------
__global__ __launch_bounds__(256) void conv_b_kernel(const float* __restrict__ w1,
                                                     const float* __restrict__ w2)
{
    int idx = blockIdx.x * blockDim.x + threadIdx.x;
    if (idx < D_HID * D_IN) {
        int n = idx / D_IN, k = idx % D_IN;
        float v = w1[(size_t)k * D_HID + n];
        __nv_bfloat16 h = __float2bfloat16_rn(v);
        g_b1_hi[idx] = h;
        g_b1_lo[idx] = __float2bfloat16_rn(v - __bfloat162float(h));
    }
    int idx2 = idx - D_HID * D_IN;
    if (idx2 >= 0 && idx2 < D_OUT * D_HID) {
        int n = idx2 / D_HID, k = idx2 % D_HID;
        float v = w2[(size_t)k * D_OUT + n];
        __nv_bfloat16 h = __float2bfloat16_rn(v);
        g_b2_hi[idx2] = h;
        g_b2_lo[idx2] = __float2bfloat16_rn(v - __bfloat162float(h));
    }
}

// ---------------------------------------------------------------------------
// mma.sync split-bf16 GEMM, 2 CTAs/SM.
//   Block tile 128x128, BK=64, 8 warps, warp tile 32x64.
//   AMODE 0: A = split(g_agg) on the fly (fp32 -> bf16 hi/lo)
//   AMODE 1: A from a_hi/a_lo via cp.async (zero-fill OOB rows)
// ---------------------------------------------------------------------------
template <int K, int NTOT, int AMODE, bool SPLIT>
__global__ __launch_bounds__(256, 2) void gemm_mma_kernel(
    const float* __restrict__ aggp,
    const __nv_bfloat16* __restrict__ a_hi,
    const __nv_bfloat16* __restrict__ a_lo,
    const __nv_bfloat16* __restrict__ b_hi,
    const __nv_bfloat16* __restrict__ b_lo,
    const float* __restrict__ bias,
    __nv_bfloat16* __restrict__ o_hi,
    __nv_bfloat16* __restrict__ o_lo,
    float* __restrict__ o_f32)
{
    constexpr uint32_t A_HI = 0, A_LO = 16384, B_HI = 32768, B_LO = 49152;

    extern __shared__ char smem[];
    const uint32_t sb = smem_u32(smem);

    const int tid   = threadIdx.x;
    const int lane  = tid & 31;
    const int wid   = tid >> 5;
    const int wm0   = (wid & 3) * 32;
    const int wn0   = (wid >> 2) * 64;
    const int row0  = blockIdx.x * 128;
    const int ncol0 = blockIdx.y * 128;

    float acc[2][8][4];
    #pragma unroll
    for (int i = 0; i < 2; ++i)
        #pragma unroll
        for (int j = 0; j < 8; ++j)
            #pragma unroll
            for (int q = 0; q < 4; ++q) acc[i][j][q] = 0.f;

    for (int kc = 0; kc < K / 64; ++kc) {
        // -------- stage A --------
        if (AMODE == 0) {
            #pragma unroll
            for (int u = tid; u < 1024; u += 256) {
                int r = u >> 3, g = u & 7;
                int row = row0 + r;
                uint4 hi = make_uint4(0, 0, 0, 0), lo = make_uint4(0, 0, 0, 0);
                if (row < N_NODES) {
                    const float* pa = aggp + (size_t)row * K + kc * 64 + g * 8;
                    float4 a0 = *reinterpret_cast<const float4*>(pa);
                    float4 a1 = *reinterpret_cast<const float4*>(pa + 4);
                    float v[8] = {a0.x, a0.y, a0.z, a0.w, a1.x, a1.y, a1.z, a1.w};
                    float h[8], l[8];
                    #pragma unroll
                    for (int j = 0; j < 8; ++j) {
                        h[j] = __bfloat162float(__float2bfloat16_rn(v[j]));
                        l[j] = v[j] - h[j];
                    }
                    hi = make_uint4(pack2bf(h[0], h[1]), pack2bf(h[2], h[3]),
                                    pack2bf(h[4], h[5]), pack2bf(h[6], h[7]));
                    lo = make_uint4(pack2bf(l[0], l[1]), pack2bf(l[2], l[3]),
                                    pack2bf(l[4], l[5]), pack2bf(l[6], l[7]));
                }
                uint32_t off = sw128((uint32_t)(r * 128 + g * 16));
                sts16(sb + A_HI + off, hi);
                sts16(sb + A_LO + off, lo);
            }
        } else {
            #pragma unroll
            for (int u = tid; u < 2048; u += 256) {
                int buf = u >> 10, rem = u & 1023;
                int r = rem >> 3, g = rem & 7;
                int row = row0 + r;
                const __nv_bfloat16* src = (buf ? a_lo : a_hi) +
                    (size_t)row * K + kc * 64 + g * 8;
                uint32_t off = sw128((uint32_t)(r * 128 + g * 16));
                cp16(sb + (buf ? A_LO : A_HI) + off, src, row < N_NODES ? 16u : 0u);
            }
        }
        // -------- stage B (cp.async) --------
        #pragma unroll
        for (int u = tid; u < 2048; u += 256) {
            int buf = u >> 10, rem = u & 1023;
            int r = rem >> 3, g = rem & 7;
            const __nv_bfloat16* src = (buf ? b_lo : b_hi) +
                (size_t)(ncol0 + r) * K + kc * 64 + g * 8;
            uint32_t off = sw128((uint32_t)(r * 128 + g * 16));
            cp16(sb + (buf ? B_LO : B_HI) + off, src, 16u);
        }
        cp_commit_wait();
        __syncthreads();

        // -------- MMA over 4 k16 steps --------
        #pragma unroll
        for (int ks = 0; ks < 4; ++ks) {
            const int kb = ks * 32;
            uint32_t ah[2][4], al[2][4];
            #pragma unroll
            for (int mi = 0; mi < 2; ++mi) {
                uint32_t off = sw128((uint32_t)((wm0 + mi * 16 + (lane & 15)) * 128 +
                                                kb + (lane >> 4) * 16));
                ldsm_x4(ah[mi], sb + A_HI + off);
                ldsm_x4(al[mi], sb + A_LO + off);
            }
            #pragma unroll
            for (int pi = 0; pi < 4; ++pi) {
                const int q = lane >> 3;
                uint32_t off = sw128((uint32_t)(
                    (wn0 + pi * 16 + ((q >> 1) << 3) + (lane & 7)) * 128 +
                    kb + (q & 1) * 16));
                uint32_t bh[4], bl[4];
                ldsm_x4(bh, sb + B_HI + off);
                ldsm_x4(bl, sb + B_LO + off);
                #pragma unroll
                for (int mi = 0; mi < 2; ++mi) {
                    #pragma unroll
                    for (int hh = 0; hh < 2; ++hh) {
                        float* c = acc[mi][pi * 2 + hh];
                        mma_bf16(c, ah[mi], bh[2 * hh], bh[2 * hh + 1]);
                        mma_bf16(c, al[mi], bh[2 * hh], bh[2 * hh + 1]);
                        mma_bf16(c, ah[mi], bl[2 * hh], bl[2 * hh + 1]);
                    }
                }
            }
        }
        __syncthreads();
    }

    // -------- epilogue --------
    #pragma unroll
    for (int mi = 0; mi < 2; ++mi) {
        #pragma unroll
        for (int ni = 0; ni < 8; ++ni) {
            int col = ncol0 + wn0 + ni * 8 + (lane & 3) * 2;
            int rbase = row0 + wm0 + mi * 16 + (lane >> 2);
            float2 bb = *reinterpret_cast<const float2*>(bias + col);
            #pragma unroll
            for (int p = 0; p < 2; ++p) {
                int row = rbase + p * 8;
                if (row >= N_NODES) continue;
                float v0 = acc[mi][ni][2 * p]     + bb.x;
                float v1 = acc[mi][ni][2 * p + 1] + bb.y;
                if (SPLIT) {
                    v0 = fmaxf(v0, 0.f); v1 = fmaxf(v1, 0.f);
                    float h0 = __bfloat162float(__float2bfloat16_rn(v0));
                    float h1 = __bfloat162float(__float2bfloat16_rn(v1));
                    *reinterpret_cast<uint32_t*>(o_hi + (size_t)row * NTOT + col) =
                        pack2bf(h0, h1);
                    *reinterpret_cast<uint32_t*>(o_lo + (size_t)row * NTOT + col) =
                        pack2bf(v0 - h0, v1 - h1);
                } else {
                    *reinterpret_cast<float2*>(o_f32 + (size_t)row * NTOT + col) =
                        make_float2(v0, v1);
                }
            }
        }
    }
}

// ---------------------------------------------------------------------------
// Launch. Inputs: x, edge_src, edge_dst, edge_val, eps, w1, b1, w2, b2
// ---------------------------------------------------------------------------
extern "C" void kernel_launch(void* const* d_in, const int* in_sizes, int n_in,
                              void* d_out, int out_size)
{
    const float* x        = (const float*)d_in[0];
    const int*   edge_src = (const int*)  d_in[1];
    const int*   edge_dst = (const int*)  d_in[2];
    const float* edge_val = (const float*)d_in[3];
    const float* eps      = (const float*)d_in[4];
    const float* w1       = (const float*)d_in[5];
    const float* b1       = (const float*)d_in[6];
    const float* w2       = (const float*)d_in[7];
    const float* b2       = (const float*)d_in[8];
    float* out = (float*)d_out;

    float* aggp;
    __nv_bfloat16 *hid_hi, *hid_lo, *b1h, *b1l, *b2h, *b2l;
    cudaGetSymbolAddress((void**)&aggp,   g_agg);
    cudaGetSymbolAddress((void**)&hid_hi, g_hid_hi);
    cudaGetSymbolAddress((void**)&hid_lo, g_hid_lo);
    cudaGetSymbolAddress((void**)&b1h, g_b1_hi);
    cudaGetSymbolAddress((void**)&b1l, g_b1_lo);
    cudaGetSymbolAddress((void**)&b2h, g_b2_hi);
    cudaGetSymbolAddress((void**)&b2l, g_b2_lo);

    // init agg = (1+eps)*x
    {
        size_t n = (size_t)N_NODES * D_IN / 4;
        init_agg_kernel<<<(int)((n + 255) / 256), 256>>>(x, eps);
    }
    // aggregation
    {
        int warps = (N_EDGES + EDGES_PER_WARP - 1) / EDGES_PER_WARP;
        agg_kernel<<<(warps * 32 + 255) / 256, 256>>>(x, edge_src, edge_dst, edge_val);
    }
    // weight transpose + split
    conv_b_kernel<<<(D_HID * D_IN + D_OUT * D_HID + 255) / 256, 256>>>(w1, w2);

    const int grid_m = (N_NODES + 127) / 128;
    constexpr int SMEM = 65536;

    // GEMM1: A = split(agg) on the fly; [N,128] x [128,256] -> hid split
    {
        auto kfn = gemm_mma_kernel<D_IN, D_HID, 0, true>;
        cudaFuncSetAttribute(kfn, cudaFuncAttributeMaxDynamicSharedMemorySize, SMEM);
        kfn<<<dim3(grid_m, D_HID / 128), 256, SMEM>>>(
            aggp, nullptr, nullptr, b1h, b1l, b1, hid_hi, hid_lo, nullptr);
    }
    // GEMM2: [N,256] x [256,128] -> out fp32
    {
        auto kfn = gemm_mma_kernel<D_HID, D_OUT, 1, false>;
        cudaFuncSetAttribute(kfn, cudaFuncAttributeMaxDynamicSharedMemorySize, SMEM);
        kfn<<<dim3(grid_m, 1), 256, SMEM>>>(
            nullptr, hid_hi, hid_lo, b2h, b2l, b2, nullptr, nullptr, out);
    }
}

// round 5
// speedup vs baseline: 2.1135x; 1.1256x over previous
#include <cuda_runtime.h>
#include <cuda_fp16.h>
#include <cstdint>

#define N_NODES 50000
#define N_EDGES 800000
#define D_IN    128
#define D_HID   256
#define D_OUT   128

// ---------------------------------------------------------------------------
// Device scratch (no cudaMalloc allowed)
// ---------------------------------------------------------------------------
__device__ float  g_agg   [(size_t)N_NODES * D_IN];
__device__ __half g_xh    [(size_t)N_NODES * D_IN];    // fp16 copy of x (gather)
__device__ __half g_hid_hi[(size_t)N_NODES * D_HID];
__device__ __half g_hid_lo[(size_t)N_NODES * D_HID];
__device__ __half g_b1h   [D_HID * D_IN];              // w1^T fp16 [256,128]
__device__ __half g_b2h   [D_OUT * D_HID];             // w2^T fp16 [128,256]

// ---------------------------------------------------------------------------
// helpers
// ---------------------------------------------------------------------------
__device__ __forceinline__ uint32_t smem_u32(const void* p) {
    uint32_t a;
    asm("{ .reg .u64 t; cvta.to.shared.u64 t, %1; cvt.u32.u64 %0, t; }" : "=r"(a) : "l"(p));
    return a;
}
__device__ __forceinline__ uint32_t sw128(uint32_t off) { return off ^ ((off >> 3) & 0x70); }

__device__ __forceinline__ uint32_t pack2h(float a, float b) {
    __half2 h = __floats2half2_rn(a, b);
    return *reinterpret_cast<uint32_t*>(&h);
}
__device__ __forceinline__ void ldsm_x4(uint32_t* r, uint32_t addr) {
    asm volatile("ldmatrix.sync.aligned.m8n8.x4.shared.b16 {%0,%1,%2,%3}, [%4];"
                 : "=r"(r[0]), "=r"(r[1]), "=r"(r[2]), "=r"(r[3]) : "r"(addr));
}
__device__ __forceinline__ void mma_f16(float* c, const uint32_t* a, uint32_t b0, uint32_t b1) {
    asm volatile("mma.sync.aligned.m16n8k16.row.col.f32.f16.f16.f32 "
                 "{%0,%1,%2,%3}, {%4,%5,%6,%7}, {%8,%9}, {%0,%1,%2,%3};"
                 : "+f"(c[0]), "+f"(c[1]), "+f"(c[2]), "+f"(c[3])
                 : "r"(a[0]), "r"(a[1]), "r"(a[2]), "r"(a[3]), "r"(b0), "r"(b1));
}
__device__ __forceinline__ void sts16(uint32_t addr, uint4 v) {
    asm volatile("st.shared.v4.b32 [%0], {%1,%2,%3,%4};"
                 :: "r"(addr), "r"(v.x), "r"(v.y), "r"(v.z), "r"(v.w) : "memory");
}
__device__ __forceinline__ void cp16(uint32_t dst, const void* src, uint32_t sz) {
    asm volatile("cp.async.cg.shared.global [%0], [%1], 16, %2;"
                 :: "r"(dst), "l"(src), "r"(sz) : "memory");
}
__device__ __forceinline__ void cp_commit_wait() {
    asm volatile("cp.async.commit_group;" ::: "memory");
    asm volatile("cp.async.wait_group 0;" ::: "memory");
}

// ---------------------------------------------------------------------------
// init: agg = (1+eps)*x  AND  xh = fp16(x)   (single read of x)
// ---------------------------------------------------------------------------
__global__ void init_kernel(const float* __restrict__ x,
                            const float* __restrict__ eps) {
    const float epsv = 1.0f + eps[0];
    size_t i = (size_t)blockIdx.x * blockDim.x + threadIdx.x;
    size_t n = (size_t)N_NODES * D_IN / 4;
    if (i < n) {
        float4 v = reinterpret_cast<const float4*>(x)[i];
        uint2 h;
        h.x = pack2h(v.x, v.y);
        h.y = pack2h(v.z, v.w);
        reinterpret_cast<uint2*>(g_xh)[i] = h;
        v.x *= epsv; v.y *= epsv; v.z *= epsv; v.w *= epsv;
        reinterpret_cast<float4*>(g_agg)[i] = v;
    }
}

// ---------------------------------------------------------------------------
// edge aggregation: gather fp16 rows, accumulate fp32, flush via atomics on
// segment change (edge_dst sorted).
// ---------------------------------------------------------------------------
#define EDGES_PER_WARP 128

__global__ __launch_bounds__(256) void agg_kernel(
    const int*   __restrict__ edge_src,
    const int*   __restrict__ edge_dst,
    const float* __restrict__ edge_val)
{
    int gtid   = blockIdx.x * blockDim.x + threadIdx.x;
    int warpId = gtid >> 5;
    int lane   = threadIdx.x & 31;

    long start = (long)warpId * EDGES_PER_WARP;
    if (start >= N_EDGES) return;
    long end = start + EDGES_PER_WARP;
    if (end > N_EDGES) end = N_EDGES;

    float ax = 0.f, ay = 0.f, az = 0.f, aw = 0.f;
    int cur_dst = edge_dst[start];

    for (long e = start; e < end; ++e) {
        int d = edge_dst[e];
        if (d != cur_dst) {
            float* o = g_agg + (size_t)cur_dst * D_IN + lane * 4;
            atomicAdd(o + 0, ax); atomicAdd(o + 1, ay);
            atomicAdd(o + 2, az); atomicAdd(o + 3, aw);
            ax = ay = az = aw = 0.f;
            cur_dst = d;
        }
        int   s = edge_src[e];
        float v = edge_val[e];
        uint2 hv = *reinterpret_cast<const uint2*>(g_xh + (size_t)s * D_IN + lane * 4);
        float2 x01 = __half22float2(*reinterpret_cast<__half2*>(&hv.x));
        float2 x23 = __half22float2(*reinterpret_cast<__half2*>(&hv.y));
        ax += v * x01.x; ay += v * x01.y; az += v * x23.x; aw += v * x23.y;
    }
    float* o = g_agg + (size_t)cur_dst * D_IN + lane * 4;
    atomicAdd(o + 0, ax); atomicAdd(o + 1, ay);
    atomicAdd(o + 2, az); atomicAdd(o + 3, aw);
}

// ---------------------------------------------------------------------------
// weight transpose -> fp16 (no split; B error ~2^-12 acceptable)
// ---------------------------------------------------------------------------
__global__ __launch_bounds__(256) void conv_b_kernel(const float* __restrict__ w1,
                                                     const float* __restrict__ w2)
{
    int idx = blockIdx.x * blockDim.x + threadIdx.x;
    if (idx < D_HID * D_IN) {
        int n = idx / D_IN, k = idx % D_IN;
        g_b1h[idx] = __float2half_rn(w1[(size_t)k * D_HID + n]);
    }
    int idx2 = idx - D_HID * D_IN;
    if (idx2 >= 0 && idx2 < D_OUT * D_HID) {
        int n = idx2 / D_HID, k = idx2 % D_HID;
        g_b2h[idx2] = __float2half_rn(w2[(size_t)k * D_OUT + n]);
    }
}

// ---------------------------------------------------------------------------
// mma.sync split-fp16 GEMM (2-term: A_hi*B + A_lo*B), 2 CTAs/SM.
//   Block tile 128x128, BK=64, 8 warps, warp tile 32x64.
//   AMODE 0: A = split(g_agg fp32) on the fly
//   AMODE 1: A hi/lo fp16 via cp.async (zero-fill OOB rows)
//   SMEM: A_HI | A_LO | B  = 3 x 16 KB
// ---------------------------------------------------------------------------
template <int K, int NTOT, int AMODE, bool SPLIT>
__global__ __launch_bounds__(256, 2) void gemm_mma_kernel(
    const float* __restrict__ aggp,
    const __half* __restrict__ a_hi,
    const __half* __restrict__ a_lo,
    const __half* __restrict__ bmat,
    const float* __restrict__ bias,
    __half* __restrict__ o_hi,
    __half* __restrict__ o_lo,
    float* __restrict__ o_f32)
{
    constexpr uint32_t A_HI = 0, A_LO = 16384, B_OF = 32768;

    extern __shared__ char smem[];
    const uint32_t sb = smem_u32(smem);

    const int tid   = threadIdx.x;
    const int lane  = tid & 31;
    const int wid   = tid >> 5;
    const int wm0   = (wid & 3) * 32;
    const int wn0   = (wid >> 2) * 64;
    const int row0  = blockIdx.x * 128;
    const int ncol0 = blockIdx.y * 128;

    float acc[2][8][4];
    #pragma unroll
    for (int i = 0; i < 2; ++i)
        #pragma unroll
        for (int j = 0; j < 8; ++j)
            #pragma unroll
            for (int q = 0; q < 4; ++q) acc[i][j][q] = 0.f;

    for (int kc = 0; kc < K / 64; ++kc) {
        // -------- stage B (cp.async, always in bounds) --------
        #pragma unroll
        for (int u = tid; u < 1024; u += 256) {
            int r = u >> 3, g = u & 7;
            const __half* src = bmat + (size_t)(ncol0 + r) * K + kc * 64 + g * 8;
            cp16(sb + B_OF + sw128((uint32_t)(r * 128 + g * 16)), src, 16u);
        }
        // -------- stage A --------
        if (AMODE == 0) {
            #pragma unroll
            for (int u = tid; u < 1024; u += 256) {
                int r = u >> 3, g = u & 7;
                int row = row0 + r;
                uint4 hi = make_uint4(0, 0, 0, 0), lo = make_uint4(0, 0, 0, 0);
                if (row < N_NODES) {
                    const float* pa = aggp + (size_t)row * K + kc * 64 + g * 8;
                    float4 a0 = *reinterpret_cast<const float4*>(pa);
                    float4 a1 = *reinterpret_cast<const float4*>(pa + 4);
                    float v[8] = {a0.x, a0.y, a0.z, a0.w, a1.x, a1.y, a1.z, a1.w};
                    float h[8], l[8];
                    #pragma unroll
                    for (int j = 0; j < 8; ++j) {
                        h[j] = __half2float(__float2half_rn(v[j]));
                        l[j] = v[j] - h[j];
                    }
                    hi = make_uint4(pack2h(h[0], h[1]), pack2h(h[2], h[3]),
                                    pack2h(h[4], h[5]), pack2h(h[6], h[7]));
                    lo = make_uint4(pack2h(l[0], l[1]), pack2h(l[2], l[3]),
                                    pack2h(l[4], l[5]), pack2h(l[6], l[7]));
                }
                uint32_t off = sw128((uint32_t)(r * 128 + g * 16));
                sts16(sb + A_HI + off, hi);
                sts16(sb + A_LO + off, lo);
            }
        } else {
            #pragma unroll
            for (int u = tid; u < 2048; u += 256) {
                int buf = u >> 10, rem = u & 1023;
                int r = rem >> 3, g = rem & 7;
                int row = row0 + r;
                const __half* src = (buf ? a_lo : a_hi) +
                    (size_t)row * K + kc * 64 + g * 8;
                uint32_t off = sw128((uint32_t)(r * 128 + g * 16));
                cp16(sb + (buf ? A_LO : A_HI) + off, src, row < N_NODES ? 16u : 0u);
            }
        }
        cp_commit_wait();
        __syncthreads();

        // -------- MMA over 4 k16 steps --------
        #pragma unroll
        for (int ks = 0; ks < 4; ++ks) {
            const int kb = ks * 32;
            uint32_t ah[2][4], al[2][4];
            #pragma unroll
            for (int mi = 0; mi < 2; ++mi) {
                uint32_t off = sw128((uint32_t)((wm0 + mi * 16 + (lane & 15)) * 128 +
                                                kb + (lane >> 4) * 16));
                ldsm_x4(ah[mi], sb + A_HI + off);
                ldsm_x4(al[mi], sb + A_LO + off);
            }
            #pragma unroll
            for (int pi = 0; pi < 4; ++pi) {
                const int q = lane >> 3;
                uint32_t off = sw128((uint32_t)(
                    (wn0 + pi * 16 + ((q >> 1) << 3) + (lane & 7)) * 128 +
                    kb + (q & 1) * 16));
                uint32_t bh[4];
                ldsm_x4(bh, sb + B_OF + off);
                #pragma unroll
                for (int mi = 0; mi < 2; ++mi) {
                    #pragma unroll
                    for (int hh = 0; hh < 2; ++hh) {
                        float* c = acc[mi][pi * 2 + hh];
                        mma_f16(c, ah[mi], bh[2 * hh], bh[2 * hh + 1]);
                        mma_f16(c, al[mi], bh[2 * hh], bh[2 * hh + 1]);
                    }
                }
            }
        }
        __syncthreads();
    }

    // -------- epilogue --------
    #pragma unroll
    for (int mi = 0; mi < 2; ++mi) {
        #pragma unroll
        for (int ni = 0; ni < 8; ++ni) {
            int col = ncol0 + wn0 + ni * 8 + (lane & 3) * 2;
            int rbase = row0 + wm0 + mi * 16 + (lane >> 2);
            float2 bb = *reinterpret_cast<const float2*>(bias + col);
            #pragma unroll
            for (int p = 0; p < 2; ++p) {
                int row = rbase + p * 8;
                if (row >= N_NODES) continue;
                float v0 = acc[mi][ni][2 * p]     + bb.x;
                float v1 = acc[mi][ni][2 * p + 1] + bb.y;
                if (SPLIT) {
                    v0 = fmaxf(v0, 0.f); v1 = fmaxf(v1, 0.f);
                    float h0 = __half2float(__float2half_rn(v0));
                    float h1 = __half2float(__float2half_rn(v1));
                    *reinterpret_cast<uint32_t*>(o_hi + (size_t)row * NTOT + col) =
                        pack2h(h0, h1);
                    *reinterpret_cast<uint32_t*>(o_lo + (size_t)row * NTOT + col) =
                        pack2h(v0 - h0, v1 - h1);
                } else {
                    *reinterpret_cast<float2*>(o_f32 + (size_t)row * NTOT + col) =
                        make_float2(v0, v1);
                }
            }
        }
    }
}

// ---------------------------------------------------------------------------
// Launch. Inputs: x, edge_src, edge_dst, edge_val, eps, w1, b1, w2, b2
// ---------------------------------------------------------------------------
extern "C" void kernel_launch(void* const* d_in, const int* in_sizes, int n_in,
                              void* d_out, int out_size)
{
    const float* x        = (const float*)d_in[0];
    const int*   edge_src = (const int*)  d_in[1];
    const int*   edge_dst = (const int*)  d_in[2];
    const float* edge_val = (const float*)d_in[3];
    const float* eps      = (const float*)d_in[4];
    const float* w1       = (const float*)d_in[5];
    const float* b1       = (const float*)d_in[6];
    const float* w2       = (const float*)d_in[7];
    const float* b2       = (const float*)d_in[8];
    float* out = (float*)d_out;

    float* aggp;
    __half *hid_hi, *hid_lo, *b1h, *b2h;
    cudaGetSymbolAddress((void**)&aggp,   g_agg);
    cudaGetSymbolAddress((void**)&hid_hi, g_hid_hi);
    cudaGetSymbolAddress((void**)&hid_lo, g_hid_lo);
    cudaGetSymbolAddress((void**)&b1h, g_b1h);
    cudaGetSymbolAddress((void**)&b2h, g_b2h);

    // init: agg = (1+eps)x, xh = fp16(x)
    {
        size_t n = (size_t)N_NODES * D_IN / 4;
        init_kernel<<<(int)((n + 255) / 256), 256>>>(x, eps);
    }
    // aggregation (fp16 gather)
    {
        int warps = (N_EDGES + EDGES_PER_WARP - 1) / EDGES_PER_WARP;
        agg_kernel<<<(warps * 32 + 255) / 256, 256>>>(edge_src, edge_dst, edge_val);
    }
    // weight transpose -> fp16
    conv_b_kernel<<<(D_HID * D_IN + D_OUT * D_HID + 255) / 256, 256>>>(w1, w2);

    const int grid_m = (N_NODES + 127) / 128;
    constexpr int SMEM = 49152;

    // GEMM1: A = split(agg); [N,128] x [128,256] -> hid split fp16
    {
        auto kfn = gemm_mma_kernel<D_IN, D_HID, 0, true>;
        cudaFuncSetAttribute(kfn, cudaFuncAttributeMaxDynamicSharedMemorySize, SMEM);
        kfn<<<dim3(grid_m, D_HID / 128), 256, SMEM>>>(
            aggp, nullptr, nullptr, b1h, b1, hid_hi, hid_lo, nullptr);
    }
    // GEMM2: [N,256] x [256,128] -> out fp32
    {
        auto kfn = gemm_mma_kernel<D_HID, D_OUT, 1, false>;
        cudaFuncSetAttribute(kfn, cudaFuncAttributeMaxDynamicSharedMemorySize, SMEM);
        kfn<<<dim3(grid_m, 1), 256, SMEM>>>(
            nullptr, hid_hi, hid_lo, b2h, b2, nullptr, nullptr, out);
    }
}